// round 15
// baseline (speedup 1.0000x reference)
#include <cuda_runtime.h>
#include <cuda_fp16.h>
#include <cuda.h>
#include <cstdint>

#define BATCH   4
#define SEQ     4096
#define HID     2048
#define NHEADS  16
#define HDIM    128
#define MTOT    (BATCH*SEQ)   /* 16384 */
#define NQKV    (3*HID)       /* 6144  */

// ---------------- scratch (device globals; no runtime alloc) ----------------
__device__ __half g_xh  [(size_t)MTOT*HID];    // fp16 x
__device__ __half g_qkvh[(size_t)MTOT*NQKV];   // qkv rows (fp16)
__device__ __half g_cth [(size_t)MTOT*HID];    // permuted context (fp16)
__device__ __half g_WT1 [(size_t)NQKV*HID];    // Wqkv^T  fp16
__device__ __half g_WT2 [(size_t)HID*HID];     // Wproj^T fp16

// ---------------- helpers ----------------
__device__ __forceinline__ uint32_t smem_u32(const void* p){
    uint32_t a;
    asm("{ .reg .u64 t; cvta.to.shared.u64 t, %1; cvt.u32.u64 %0, t; }"
        : "=r"(a) : "l"(p));
    return a;
}
#define LDSM4(rr, addr) \
    asm volatile("ldmatrix.sync.aligned.m8n8.x4.shared.b16 {%0,%1,%2,%3}, [%4];" \
        : "=r"((rr)[0]),"=r"((rr)[1]),"=r"((rr)[2]),"=r"((rr)[3]) : "r"(addr))

__device__ __forceinline__ void mma16(float* c, const uint32_t* a,
                                      uint32_t b0, uint32_t b1){
    asm volatile("mma.sync.aligned.m16n8k16.row.col.f32.f16.f16.f32 "
        "{%0,%1,%2,%3},{%4,%5,%6,%7},{%8,%9},{%0,%1,%2,%3};"
        : "+f"(c[0]),"+f"(c[1]),"+f"(c[2]),"+f"(c[3])
        : "r"(a[0]),"r"(a[1]),"r"(a[2]),"r"(a[3]), "r"(b0),"r"(b1));
}

#define MBAR_INIT(a, n) \
    asm volatile("mbarrier.init.shared.b64 [%0], %1;" :: "r"(a), "r"(n) : "memory")
#define MBAR_EXPECT_TX(a, bytes) \
    asm volatile("mbarrier.arrive.expect_tx.shared.b64 _, [%0], %1;" \
        :: "r"(a), "r"(bytes) : "memory")
#define MBAR_WAIT(a, ph) do { \
    uint32_t _m=(a), _p=(ph), _d; \
    asm volatile("{\n\t.reg .pred p;\n\t" \
        "mbarrier.try_wait.parity.acquire.cta.shared::cta.b64 p, [%1], %2;\n\t" \
        "selp.b32 %0, 1, 0, p;\n\t}" : "=r"(_d) : "r"(_m), "r"(_p) : "memory"); \
    if(!_d){ asm volatile("{\n\t.reg .pred P1;\n\t" \
        "W%=:\n\tmbarrier.try_wait.parity.acquire.cta.shared::cta.b64 P1, [%0], %1, 0x989680;\n\t" \
        "@P1 bra.uni D%=;\n\tbra.uni W%=;\n\tD%=:\n\t}" \
        :: "r"(_m), "r"(_p) : "memory"); } \
} while(0)

#define TMA_LOAD_2D(sm, map, cx, cy, mb) \
    asm volatile("cp.async.bulk.tensor.2d.shared::cta.global.tile.mbarrier::complete_tx::bytes " \
        "[%0], [%1, {%2, %3}], [%4];" \
        :: "r"(sm), "l"(map), "r"(cx), "r"(cy), "r"(mb) : "memory")

// ---------------------------------------------------------------------------
// FP16 mma.sync GEMM (fp32 accumulate), TMA(SW128) loads + ldmatrix feed.
// C[M x N] = A[M x K] * BT[N x K]^T + bias.
// CTA: 128 threads (4 warps, 2x2), tile 128x128, warp tile 64x64.
// KC=64 halves, 3 stages (32KB each), 2 CTAs/SM, 1 barrier/chunk.
// Fragments are DOUBLE-BUFFERED across ksteps: kstep j+1's 8 LDSM issue
// before kstep j's 32 MMAs, hiding LDSM latency under the MMA chain.
// OT = __half (gemm0 -> qkv fp16) or float (gemm1 -> final output).
// ---------------------------------------------------------------------------
#define STG_BYTES 32768                /* 16KB A (128x128B) + 16KB B */
#define STAGES    3
#define DSM_BYTES (STAGES*STG_BYTES + 1024)

template<typename OT>
__global__ void __launch_bounds__(128, 2)
hgemm(const __grid_constant__ CUtensorMap tmA,
      const __grid_constant__ CUtensorMap tmB,
      const float* __restrict__ bias, OT* __restrict__ C,
      int K, int N)
{
    extern __shared__ char dsm_raw[];
    __shared__ __align__(8) uint64_t mbar[STAGES];
    const uint32_t smem = (smem_u32(dsm_raw) + 1023u) & ~1023u;
    const int tid = threadIdx.x, warp = tid>>5, lane = tid&31;
    const int g = lane>>2, t = lane&3;
    const int wm = warp>>1, wn = warp&1;             // 2 x 2 warps, 64x64 each
    const int m0 = blockIdx.y*128, n0 = blockIdx.x*128;
    const int NCH = K/64;

    // SW128 ldmatrix per-lane addressing
    const int m8 = lane>>3, r8 = lane&7;
    // A: matrix m -> row-half (m&1)*8, k-col (m>>1)
    const uint32_t abase = (uint32_t)((wm*64 + (m8&1)*8 + r8) * 128);
    const uint32_t acol0 = (uint32_t)(m8>>1);
    // B: matrix m -> n-half (m>>1)*8, k-col (m&1)
    const uint32_t bbase = (uint32_t)(16384 + (wn*64 + (m8>>1)*8 + r8) * 128);
    const uint32_t bcol0 = (uint32_t)(m8&1);
    uint32_t axor[4], bxor[4];
    #pragma unroll
    for(int ks=0; ks<4; ++ks){
        axor[ks] = (((acol0 + 2*ks) ^ (uint32_t)r8) << 4);
        bxor[ks] = (((bcol0 + 2*ks) ^ (uint32_t)r8) << 4);
    }

    if (tid == 0){
        #pragma unroll
        for(int s=0;s<STAGES;++s) MBAR_INIT(smem_u32(&mbar[s]), 1);
    }
    __syncthreads();

    // prologue: issue chunks 0 and 1
    if (tid == 0){
        #pragma unroll
        for(int c=0;c<2;++c){
            uint32_t mb = smem_u32(&mbar[c]);
            MBAR_EXPECT_TX(mb, STG_BYTES);
            TMA_LOAD_2D(smem + c*STG_BYTES,         &tmA, c*64, m0, mb);
            TMA_LOAD_2D(smem + c*STG_BYTES + 16384, &tmB, c*64, n0, mb);
        }
    }

    float acc[4][8][4];
    #pragma unroll
    for(int i=0;i<4;++i)
        #pragma unroll
        for(int j=0;j<8;++j)
            #pragma unroll
            for(int e=0;e<4;++e) acc[i][j][e]=0.f;

    int s = 0, ph = 0;
    for(int c=0;c<NCH;++c){
        MBAR_WAIT(smem_u32(&mbar[s]), ph);
        __syncthreads();
        // issue chunk c+2 into stage (c+2)%3 == (c-1)%3 (drained by barrier)
        if (tid == 0 && c+2 < NCH){
            int s2 = s+2; if (s2 >= STAGES) s2 -= STAGES;
            uint32_t mb = smem_u32(&mbar[s2]);
            MBAR_EXPECT_TX(mb, STG_BYTES);
            TMA_LOAD_2D(smem + s2*STG_BYTES,         &tmA, (c+2)*64, m0, mb);
            TMA_LOAD_2D(smem + s2*STG_BYTES + 16384, &tmB, (c+2)*64, n0, mb);
        }

        const uint32_t stg = smem + s*STG_BYTES;
        uint32_t af[2][4][4], bf[2][4][4];
        // preload kstep 0 into buffer 0
        #pragma unroll
        for(int i=0;i<4;++i)   LDSM4(af[0][i], stg + abase + i*2048 + axor[0]);
        #pragma unroll
        for(int jp=0;jp<4;++jp) LDSM4(bf[0][jp], stg + bbase + jp*2048 + bxor[0]);

        #pragma unroll
        for(int ks=0; ks<4; ++ks){
            const int cur = ks & 1, nxt = cur ^ 1;
            if (ks < 3){                             // prefetch kstep ks+1
                #pragma unroll
                for(int i=0;i<4;++i)
                    LDSM4(af[nxt][i], stg + abase + i*2048 + axor[ks+1]);
                #pragma unroll
                for(int jp=0;jp<4;++jp)
                    LDSM4(bf[nxt][jp], stg + bbase + jp*2048 + bxor[ks+1]);
            }
            #pragma unroll
            for(int i=0;i<4;++i){
                #pragma unroll
                for(int jp=0;jp<4;++jp){
                    mma16(acc[i][jp*2  ], af[cur][i], bf[cur][jp][0], bf[cur][jp][1]);
                    mma16(acc[i][jp*2+1], af[cur][i], bf[cur][jp][2], bf[cur][jp][3]);
                }
            }
        }
        if (++s == STAGES){ s = 0; ph ^= 1; }
    }

    // epilogue: +bias, store as OT
    #pragma unroll
    for(int i=0;i<4;++i){
        #pragma unroll
        for(int j=0;j<8;++j){
            int r0 = m0 + wm*64 + i*16 + g;
            int c0 = n0 + wn*64 + j*8 + 2*t;
            float bx = bias[c0], by = bias[c0+1];
            float v00 = acc[i][j][0]+bx, v01 = acc[i][j][1]+by;
            float v10 = acc[i][j][2]+bx, v11 = acc[i][j][3]+by;
            if (sizeof(OT) == 2){
                *(__half2*)((__half*)C + (size_t)r0*N + c0)     = __floats2half2_rn(v00, v01);
                *(__half2*)((__half*)C + (size_t)(r0+8)*N + c0) = __floats2half2_rn(v10, v11);
            } else {
                *(float2*)((float*)C + (size_t)r0*N + c0)     = make_float2(v00, v01);
                *(float2*)((float*)C + (size_t)(r0+8)*N + c0) = make_float2(v10, v11);
            }
        }
    }
}

// ---------------------------------------------------------------------------
// prepass: convert x fp32 -> fp16
// ---------------------------------------------------------------------------
__global__ void __launch_bounds__(1024)
tohalf_kernel(const float* __restrict__ x, __half* __restrict__ y, int n4)
{
    int i = blockIdx.x*blockDim.x + threadIdx.x;
    if (i < n4){
        float4 v = ((const float4*)x)[i];
        ((__half2*)y)[2*i]   = __floats2half2_rn(v.x, v.y);
        ((__half2*)y)[2*i+1] = __floats2half2_rn(v.z, v.w);
    }
}

// ---------------------------------------------------------------------------
// prepass: transpose + convert. W[K][N] fp32 -> WT[N][K] fp16
// ---------------------------------------------------------------------------
__global__ void __launch_bounds__(256)
transpose_kernel(const float* __restrict__ W, __half* __restrict__ WT,
                 int K, int N)
{
    __shared__ float tbuf[32][33];
    const int n0 = blockIdx.x*32, k0 = blockIdx.y*32;
    const int tx = threadIdx.x & 31, ty = threadIdx.x >> 5;  // 32 x 8
    #pragma unroll
    for(int i=0;i<4;++i)
        tbuf[ty+8*i][tx] = W[(size_t)(k0+ty+8*i)*N + n0+tx];
    __syncthreads();
    #pragma unroll
    for(int i=0;i<4;++i)
        WT[(size_t)(n0+ty+8*i)*K + k0+tx] = __float2half_rn(tbuf[tx][ty+8*i]);
}

// ---------------------------------------------------------------------------
// Per-position head-mixing attention (reference einsum), fp32 internal math.
// Reads fp16 qkv, writes g_cth (fp16) in transpose(0,2,1,3).reshape layout.
// ---------------------------------------------------------------------------
__global__ void __launch_bounds__(128)
attn_kernel()
{
    __shared__ float S[48*132];

    const int tid = threadIdx.x;
    const size_t pos = blockIdx.x;               // b*4096 + s
    const __half* row = g_qkvh + pos*NQKV;

    #pragma unroll
    for(int it=0; it<6; ++it){
        int idx = tid + 128*it;                  // 768 x 16B (8 halves each)
        uint4 v = ((const uint4*)row)[idx];
        const __half2* hp = (const __half2*)&v;
        int r = idx>>4, c = (idx&15)<<3;
        float* d = S + r*132 + c;
        #pragma unroll
        for(int k=0;k<4;++k){
            float2 f = __half22float2(hp[k]);
            d[2*k] = f.x; d[2*k+1] = f.y;
        }
    }
    __syncthreads();

    const int h = tid>>3, i = tid&7;
    const float4* Q4 = (const float4*)(S + h*132);
    const float4* K0 = (const float4*)(S + (16+i)*132);
    const float4* K1 = (const float4*)(S + (24+i)*132);

    float s0=0.f, s1=0.f;
    #pragma unroll
    for(int d=0; d<32; ++d){
        float4 q = Q4[d], a = K0[d], b = K1[d];
        s0 += q.x*a.x + q.y*a.y + q.z*a.z + q.w*a.w;
        s1 += q.x*b.x + q.y*b.y + q.z*b.z + q.w*b.w;
    }
    const float sc = 0.08838834764831845f;       // 1/sqrt(128)
    s0 *= sc; s1 *= sc;

    float m = fmaxf(s0, s1);
    m = fmaxf(m, __shfl_xor_sync(0xffffffffu, m, 1));
    m = fmaxf(m, __shfl_xor_sync(0xffffffffu, m, 2));
    m = fmaxf(m, __shfl_xor_sync(0xffffffffu, m, 4));
    float e0 = __expf(s0 - m), e1 = __expf(s1 - m);
    float sum = e0 + e1;
    sum += __shfl_xor_sync(0xffffffffu, sum, 1);
    sum += __shfl_xor_sync(0xffffffffu, sum, 2);
    sum += __shfl_xor_sync(0xffffffffu, sum, 4);
    float inv = 1.f/sum;
    float w0 = e0*inv, w1 = e1*inv;

    float wv[16];
    #pragma unroll
    for(int j=0;j<8;++j){
        wv[j]   = __shfl_sync(0xffffffffu, w0, j, 8);
        wv[j+8] = __shfl_sync(0xffffffffu, w1, j, 8);
    }

    const int b = (int)(pos>>12), s = (int)(pos&4095);
    __half* orow = g_cth + ((size_t)(b*SEQ + h*256 + (s>>4)))*HID + (size_t)(s&15)*HDIM;
    #pragma unroll
    for(int j=0;j<4;++j){
        int d4 = i + 8*j;
        float4 acc = make_float4(0.f,0.f,0.f,0.f);
        #pragma unroll
        for(int tt=0;tt<16;++tt){
            float4 v = *(const float4*)(S + (32+tt)*132 + (d4<<2));
            acc.x += wv[tt]*v.x; acc.y += wv[tt]*v.y;
            acc.z += wv[tt]*v.z; acc.w += wv[tt]*v.w;
        }
        ((__half2*)(orow + (d4<<2)))[0] = __floats2half2_rn(acc.x, acc.y);
        ((__half2*)(orow + (d4<<2)))[1] = __floats2half2_rn(acc.z, acc.w);
    }
}

// ---------------------------------------------------------------------------
typedef CUresult (*EncodeTiledFn)(
    CUtensorMap*, CUtensorMapDataType, cuuint32_t, void*,
    const cuuint64_t*, const cuuint64_t*, const cuuint32_t*, const cuuint32_t*,
    CUtensorMapInterleave, CUtensorMapSwizzle, CUtensorMapL2promotion,
    CUtensorMapFloatOOBfill);

static void make_map_fp16(EncodeTiledFn fn, CUtensorMap* m, void* ptr,
                          unsigned long long rows)
{
    cuuint64_t dims[2]    = {2048ull, rows};     // K elems contiguous, rows
    cuuint64_t strides[1] = {4096ull};           // row stride bytes (K*2)
    cuuint32_t box[2]     = {64u, 128u};         // 64 halves (128B) x 128 rows
    cuuint32_t es[2]      = {1u, 1u};
    fn(m, CU_TENSOR_MAP_DATA_TYPE_FLOAT16, 2, ptr, dims, strides, box, es,
       CU_TENSOR_MAP_INTERLEAVE_NONE, CU_TENSOR_MAP_SWIZZLE_128B,
       CU_TENSOR_MAP_L2_PROMOTION_L2_128B, CU_TENSOR_MAP_FLOAT_OOB_FILL_NONE);
}

extern "C" void kernel_launch(void* const* d_in, const int* in_sizes, int n_in,
                              void* d_out, int out_size)
{
    const float* x     = (const float*)d_in[0];
    const float* Wqkv  = (const float*)d_in[1];
    const float* bqkv  = (const float*)d_in[2];
    const float* Wproj = (const float*)d_in[3];
    const float* bproj = (const float*)d_in[4];
    float* out = (float*)d_out;

    cudaFuncSetAttribute(hgemm<__half>, cudaFuncAttributeMaxDynamicSharedMemorySize,
                         DSM_BYTES);
    cudaFuncSetAttribute(hgemm<float>,  cudaFuncAttributeMaxDynamicSharedMemorySize,
                         DSM_BYTES);

    __half *xh, *qkvh, *cth, *wt1, *wt2;
    cudaGetSymbolAddress((void**)&xh,   g_xh);
    cudaGetSymbolAddress((void**)&qkvh, g_qkvh);
    cudaGetSymbolAddress((void**)&cth,  g_cth);
    cudaGetSymbolAddress((void**)&wt1,  g_WT1);
    cudaGetSymbolAddress((void**)&wt2,  g_WT2);

    // driver entry point via runtime (no -lcuda link dependency)
    EncodeTiledFn enc = nullptr;
    cudaDriverEntryPointQueryResult qr;
    cudaGetDriverEntryPointByVersion("cuTensorMapEncodeTiled", (void**)&enc,
                                     12050, cudaEnableDefault, &qr);

    CUtensorMap tmA0, tmB0, tmA1, tmB1;
    make_map_fp16(enc, &tmA0, xh,  (unsigned long long)MTOT);
    make_map_fp16(enc, &tmB0, wt1, (unsigned long long)NQKV);
    make_map_fp16(enc, &tmA1, cth, (unsigned long long)MTOT);
    make_map_fp16(enc, &tmB1, wt2, (unsigned long long)HID);

    const int n4 = MTOT*HID/4;
    tohalf_kernel<<<(n4+1023)/1024, 1024>>>(x, xh, n4);
    transpose_kernel<<<dim3(NQKV/32, HID/32), 256>>>(Wqkv, wt1, HID, NQKV);
    transpose_kernel<<<dim3(HID/32,  HID/32), 256>>>(Wproj, wt2, HID, HID);

    hgemm<__half><<<dim3(NQKV/128, MTOT/128), 128, DSM_BYTES>>>(
        tmA0, tmB0, bqkv, qkvh, HID, NQKV);
    attn_kernel<<<MTOT, 128>>>();
    hgemm<float><<<dim3(HID/128, MTOT/128), 128, DSM_BYTES>>>(
        tmA1, tmB1, bproj, out, HID, HID);
}

// round 16
// speedup vs baseline: 1.0433x; 1.0433x over previous
#include <cuda_runtime.h>
#include <cuda_fp16.h>
#include <cuda.h>
#include <cstdint>

#define BATCH   4
#define SEQ     4096
#define HID     2048
#define NHEADS  16
#define HDIM    128
#define MTOT    (BATCH*SEQ)   /* 16384 */
#define NQKV    (3*HID)       /* 6144  */

// ---------------- scratch (device globals; no runtime alloc) ----------------
__device__ __half g_xh  [(size_t)MTOT*HID];    // fp16 x
__device__ __half g_qkvh[(size_t)MTOT*NQKV];   // qkv rows (fp16)
__device__ __half g_cth [(size_t)MTOT*HID];    // permuted context (fp16)
__device__ __half g_WT1 [(size_t)NQKV*HID];    // Wqkv^T  fp16
__device__ __half g_WT2 [(size_t)HID*HID];     // Wproj^T fp16

// ---------------- helpers ----------------
__device__ __forceinline__ uint32_t smem_u32(const void* p){
    uint32_t a;
    asm("{ .reg .u64 t; cvta.to.shared.u64 t, %1; cvt.u32.u64 %0, t; }"
        : "=r"(a) : "l"(p));
    return a;
}
#define LDSM4(rr, addr) \
    asm volatile("ldmatrix.sync.aligned.m8n8.x4.shared.b16 {%0,%1,%2,%3}, [%4];" \
        : "=r"((rr)[0]),"=r"((rr)[1]),"=r"((rr)[2]),"=r"((rr)[3]) : "r"(addr))

__device__ __forceinline__ void mma16(float* c, const uint32_t* a,
                                      uint32_t b0, uint32_t b1){
    asm volatile("mma.sync.aligned.m16n8k16.row.col.f32.f16.f16.f32 "
        "{%0,%1,%2,%3},{%4,%5,%6,%7},{%8,%9},{%0,%1,%2,%3};"
        : "+f"(c[0]),"+f"(c[1]),"+f"(c[2]),"+f"(c[3])
        : "r"(a[0]),"r"(a[1]),"r"(a[2]),"r"(a[3]), "r"(b0),"r"(b1));
}

#define MBAR_INIT(a, n) \
    asm volatile("mbarrier.init.shared.b64 [%0], %1;" :: "r"(a), "r"(n) : "memory")
#define MBAR_EXPECT_TX(a, bytes) \
    asm volatile("mbarrier.arrive.expect_tx.shared.b64 _, [%0], %1;" \
        :: "r"(a), "r"(bytes) : "memory")
#define MBAR_WAIT(a, ph) do { \
    uint32_t _m=(a), _p=(ph), _d; \
    asm volatile("{\n\t.reg .pred p;\n\t" \
        "mbarrier.try_wait.parity.acquire.cta.shared::cta.b64 p, [%1], %2;\n\t" \
        "selp.b32 %0, 1, 0, p;\n\t}" : "=r"(_d) : "r"(_m), "r"(_p) : "memory"); \
    if(!_d){ asm volatile("{\n\t.reg .pred P1;\n\t" \
        "W%=:\n\tmbarrier.try_wait.parity.acquire.cta.shared::cta.b64 P1, [%0], %1, 0x989680;\n\t" \
        "@P1 bra.uni D%=;\n\tbra.uni W%=;\n\tD%=:\n\t}" \
        :: "r"(_m), "r"(_p) : "memory"); } \
} while(0)

#define TMA_LOAD_2D(sm, map, cx, cy, mb) \
    asm volatile("cp.async.bulk.tensor.2d.shared::cta.global.tile.mbarrier::complete_tx::bytes " \
        "[%0], [%1, {%2, %3}], [%4];" \
        :: "r"(sm), "l"(map), "r"(cx), "r"(cy), "r"(mb) : "memory")

// ---------------------------------------------------------------------------
// FP16 mma.sync GEMM (fp32 accumulate), TMA(SW128) loads + ldmatrix feed.
// C[M x N] = A[M x K] * BT[N x K]^T + bias.
// CTA: 128 threads (4 warps, 2x2), tile 128x128, warp tile 64x64.
// KC=64 halves, 3 stages (32KB each), 2 CTAs/SM, 1 barrier/chunk.
// Mainloop order: syncthreads (stage-drain proof) -> issue TMA(c+2) ->
// wait data(c) -> compute. TMA for the next chunk enters flight before we
// block on the current chunk's arrival.
// OT = __half (gemm0 -> qkv fp16) or float (gemm1 -> final output).
// ---------------------------------------------------------------------------
#define STG_BYTES 32768                /* 16KB A (128x128B) + 16KB B */
#define STAGES    3
#define DSM_BYTES (STAGES*STG_BYTES + 1024)

template<typename OT>
__global__ void __launch_bounds__(128, 2)
hgemm(const __grid_constant__ CUtensorMap tmA,
      const __grid_constant__ CUtensorMap tmB,
      const float* __restrict__ bias, OT* __restrict__ C,
      int K, int N)
{
    extern __shared__ char dsm_raw[];
    __shared__ __align__(8) uint64_t mbar[STAGES];
    const uint32_t smem = (smem_u32(dsm_raw) + 1023u) & ~1023u;
    const int tid = threadIdx.x, warp = tid>>5, lane = tid&31;
    const int g = lane>>2, t = lane&3;
    const int wm = warp>>1, wn = warp&1;             // 2 x 2 warps, 64x64 each
    const int m0 = blockIdx.y*128, n0 = blockIdx.x*128;
    const int NCH = K/64;

    // SW128 ldmatrix per-lane addressing
    const int m8 = lane>>3, r8 = lane&7;
    // A: matrix m -> row-half (m&1)*8, k-col (m>>1)
    const uint32_t abase = (uint32_t)((wm*64 + (m8&1)*8 + r8) * 128);
    const uint32_t acol0 = (uint32_t)(m8>>1);
    // B: matrix m -> n-half (m>>1)*8, k-col (m&1)
    const uint32_t bbase = (uint32_t)(16384 + (wn*64 + (m8>>1)*8 + r8) * 128);
    const uint32_t bcol0 = (uint32_t)(m8&1);
    uint32_t axor[4], bxor[4];
    #pragma unroll
    for(int ks=0; ks<4; ++ks){
        axor[ks] = (((acol0 + 2*ks) ^ (uint32_t)r8) << 4);
        bxor[ks] = (((bcol0 + 2*ks) ^ (uint32_t)r8) << 4);
    }

    if (tid == 0){
        #pragma unroll
        for(int s=0;s<STAGES;++s) MBAR_INIT(smem_u32(&mbar[s]), 1);
    }
    __syncthreads();

    // prologue: issue chunks 0 and 1
    if (tid == 0){
        #pragma unroll
        for(int c=0;c<2;++c){
            uint32_t mb = smem_u32(&mbar[c]);
            MBAR_EXPECT_TX(mb, STG_BYTES);
            TMA_LOAD_2D(smem + c*STG_BYTES,         &tmA, c*64, m0, mb);
            TMA_LOAD_2D(smem + c*STG_BYTES + 16384, &tmB, c*64, n0, mb);
        }
    }

    float acc[4][8][4];
    #pragma unroll
    for(int i=0;i<4;++i)
        #pragma unroll
        for(int j=0;j<8;++j)
            #pragma unroll
            for(int e=0;e<4;++e) acc[i][j][e]=0.f;

    int s = 0, ph = 0;
    for(int c=0;c<NCH;++c){
        __syncthreads();   // all warps done reading stage (c-1)%3
        // issue chunk c+2 into stage (c+2)%3 == (c-1)%3 BEFORE blocking on c
        if (tid == 0 && c+2 < NCH){
            int s2 = s+2; if (s2 >= STAGES) s2 -= STAGES;
            uint32_t mb = smem_u32(&mbar[s2]);
            MBAR_EXPECT_TX(mb, STG_BYTES);
            TMA_LOAD_2D(smem + s2*STG_BYTES,         &tmA, (c+2)*64, m0, mb);
            TMA_LOAD_2D(smem + s2*STG_BYTES + 16384, &tmB, (c+2)*64, n0, mb);
        }
        MBAR_WAIT(smem_u32(&mbar[s]), ph);

        const uint32_t stg = smem + s*STG_BYTES;
        #pragma unroll
        for(int ks=0; ks<4; ++ks){
            uint32_t af[4][4], bf[4][4];
            #pragma unroll
            for(int i=0;i<4;++i)   LDSM4(af[i], stg + abase + i*2048 + axor[ks]);
            #pragma unroll
            for(int jp=0;jp<4;++jp) LDSM4(bf[jp], stg + bbase + jp*2048 + bxor[ks]);
            #pragma unroll
            for(int i=0;i<4;++i){
                #pragma unroll
                for(int jp=0;jp<4;++jp){
                    mma16(acc[i][jp*2  ], af[i], bf[jp][0], bf[jp][1]);
                    mma16(acc[i][jp*2+1], af[i], bf[jp][2], bf[jp][3]);
                }
            }
        }
        if (++s == STAGES){ s = 0; ph ^= 1; }
    }

    // epilogue: +bias, store as OT
    #pragma unroll
    for(int i=0;i<4;++i){
        #pragma unroll
        for(int j=0;j<8;++j){
            int r0 = m0 + wm*64 + i*16 + g;
            int c0 = n0 + wn*64 + j*8 + 2*t;
            float bx = bias[c0], by = bias[c0+1];
            float v00 = acc[i][j][0]+bx, v01 = acc[i][j][1]+by;
            float v10 = acc[i][j][2]+bx, v11 = acc[i][j][3]+by;
            if (sizeof(OT) == 2){
                *(__half2*)((__half*)C + (size_t)r0*N + c0)     = __floats2half2_rn(v00, v01);
                *(__half2*)((__half*)C + (size_t)(r0+8)*N + c0) = __floats2half2_rn(v10, v11);
            } else {
                *(float2*)((float*)C + (size_t)r0*N + c0)     = make_float2(v00, v01);
                *(float2*)((float*)C + (size_t)(r0+8)*N + c0) = make_float2(v10, v11);
            }
        }
    }
}

// ---------------------------------------------------------------------------
// prepass: convert x fp32 -> fp16
// ---------------------------------------------------------------------------
__global__ void __launch_bounds__(1024)
tohalf_kernel(const float* __restrict__ x, __half* __restrict__ y, int n4)
{
    int i = blockIdx.x*blockDim.x + threadIdx.x;
    if (i < n4){
        float4 v = ((const float4*)x)[i];
        ((__half2*)y)[2*i]   = __floats2half2_rn(v.x, v.y);
        ((__half2*)y)[2*i+1] = __floats2half2_rn(v.z, v.w);
    }
}

// ---------------------------------------------------------------------------
// prepass: transpose + convert. W[K][N] fp32 -> WT[N][K] fp16
// ---------------------------------------------------------------------------
__global__ void __launch_bounds__(256)
transpose_kernel(const float* __restrict__ W, __half* __restrict__ WT,
                 int K, int N)
{
    __shared__ float tbuf[32][33];
    const int n0 = blockIdx.x*32, k0 = blockIdx.y*32;
    const int tx = threadIdx.x & 31, ty = threadIdx.x >> 5;  // 32 x 8
    #pragma unroll
    for(int i=0;i<4;++i)
        tbuf[ty+8*i][tx] = W[(size_t)(k0+ty+8*i)*N + n0+tx];
    __syncthreads();
    #pragma unroll
    for(int i=0;i<4;++i)
        WT[(size_t)(n0+ty+8*i)*K + k0+tx] = __float2half_rn(tbuf[tx][ty+8*i]);
}

// ---------------------------------------------------------------------------
// Per-position head-mixing attention (reference einsum), fp32 internal math.
// Reads fp16 qkv, writes g_cth (fp16) in transpose(0,2,1,3).reshape layout.
// ---------------------------------------------------------------------------
__global__ void __launch_bounds__(128)
attn_kernel()
{
    __shared__ float S[48*132];

    const int tid = threadIdx.x;
    const size_t pos = blockIdx.x;               // b*4096 + s
    const __half* row = g_qkvh + pos*NQKV;

    #pragma unroll
    for(int it=0; it<6; ++it){
        int idx = tid + 128*it;                  // 768 x 16B (8 halves each)
        uint4 v = ((const uint4*)row)[idx];
        const __half2* hp = (const __half2*)&v;
        int r = idx>>4, c = (idx&15)<<3;
        float* d = S + r*132 + c;
        #pragma unroll
        for(int k=0;k<4;++k){
            float2 f = __half22float2(hp[k]);
            d[2*k] = f.x; d[2*k+1] = f.y;
        }
    }
    __syncthreads();

    const int h = tid>>3, i = tid&7;
    const float4* Q4 = (const float4*)(S + h*132);
    const float4* K0 = (const float4*)(S + (16+i)*132);
    const float4* K1 = (const float4*)(S + (24+i)*132);

    float s0=0.f, s1=0.f;
    #pragma unroll
    for(int d=0; d<32; ++d){
        float4 q = Q4[d], a = K0[d], b = K1[d];
        s0 += q.x*a.x + q.y*a.y + q.z*a.z + q.w*a.w;
        s1 += q.x*b.x + q.y*b.y + q.z*b.z + q.w*b.w;
    }
    const float sc = 0.08838834764831845f;       // 1/sqrt(128)
    s0 *= sc; s1 *= sc;

    float m = fmaxf(s0, s1);
    m = fmaxf(m, __shfl_xor_sync(0xffffffffu, m, 1));
    m = fmaxf(m, __shfl_xor_sync(0xffffffffu, m, 2));
    m = fmaxf(m, __shfl_xor_sync(0xffffffffu, m, 4));
    float e0 = __expf(s0 - m), e1 = __expf(s1 - m);
    float sum = e0 + e1;
    sum += __shfl_xor_sync(0xffffffffu, sum, 1);
    sum += __shfl_xor_sync(0xffffffffu, sum, 2);
    sum += __shfl_xor_sync(0xffffffffu, sum, 4);
    float inv = 1.f/sum;
    float w0 = e0*inv, w1 = e1*inv;

    float wv[16];
    #pragma unroll
    for(int j=0;j<8;++j){
        wv[j]   = __shfl_sync(0xffffffffu, w0, j, 8);
        wv[j+8] = __shfl_sync(0xffffffffu, w1, j, 8);
    }

    const int b = (int)(pos>>12), s = (int)(pos&4095);
    __half* orow = g_cth + ((size_t)(b*SEQ + h*256 + (s>>4)))*HID + (size_t)(s&15)*HDIM;
    #pragma unroll
    for(int j=0;j<4;++j){
        int d4 = i + 8*j;
        float4 acc = make_float4(0.f,0.f,0.f,0.f);
        #pragma unroll
        for(int tt=0;tt<16;++tt){
            float4 v = *(const float4*)(S + (32+tt)*132 + (d4<<2));
            acc.x += wv[tt]*v.x; acc.y += wv[tt]*v.y;
            acc.z += wv[tt]*v.z; acc.w += wv[tt]*v.w;
        }
        ((__half2*)(orow + (d4<<2)))[0] = __floats2half2_rn(acc.x, acc.y);
        ((__half2*)(orow + (d4<<2)))[1] = __floats2half2_rn(acc.z, acc.w);
    }
}

// ---------------------------------------------------------------------------
typedef CUresult (*EncodeTiledFn)(
    CUtensorMap*, CUtensorMapDataType, cuuint32_t, void*,
    const cuuint64_t*, const cuuint64_t*, const cuuint32_t*, const cuuint32_t*,
    CUtensorMapInterleave, CUtensorMapSwizzle, CUtensorMapL2promotion,
    CUtensorMapFloatOOBfill);

static void make_map_fp16(EncodeTiledFn fn, CUtensorMap* m, void* ptr,
                          unsigned long long rows)
{
    cuuint64_t dims[2]    = {2048ull, rows};     // K elems contiguous, rows
    cuuint64_t strides[1] = {4096ull};           // row stride bytes (K*2)
    cuuint32_t box[2]     = {64u, 128u};         // 64 halves (128B) x 128 rows
    cuuint32_t es[2]      = {1u, 1u};
    fn(m, CU_TENSOR_MAP_DATA_TYPE_FLOAT16, 2, ptr, dims, strides, box, es,
       CU_TENSOR_MAP_INTERLEAVE_NONE, CU_TENSOR_MAP_SWIZZLE_128B,
       CU_TENSOR_MAP_L2_PROMOTION_L2_128B, CU_TENSOR_MAP_FLOAT_OOB_FILL_NONE);
}

extern "C" void kernel_launch(void* const* d_in, const int* in_sizes, int n_in,
                              void* d_out, int out_size)
{
    const float* x     = (const float*)d_in[0];
    const float* Wqkv  = (const float*)d_in[1];
    const float* bqkv  = (const float*)d_in[2];
    const float* Wproj = (const float*)d_in[3];
    const float* bproj = (const float*)d_in[4];
    float* out = (float*)d_out;

    cudaFuncSetAttribute(hgemm<__half>, cudaFuncAttributeMaxDynamicSharedMemorySize,
                         DSM_BYTES);
    cudaFuncSetAttribute(hgemm<float>,  cudaFuncAttributeMaxDynamicSharedMemorySize,
                         DSM_BYTES);

    __half *xh, *qkvh, *cth, *wt1, *wt2;
    cudaGetSymbolAddress((void**)&xh,   g_xh);
    cudaGetSymbolAddress((void**)&qkvh, g_qkvh);
    cudaGetSymbolAddress((void**)&cth,  g_cth);
    cudaGetSymbolAddress((void**)&wt1,  g_WT1);
    cudaGetSymbolAddress((void**)&wt2,  g_WT2);

    // driver entry point via runtime (no -lcuda link dependency)
    EncodeTiledFn enc = nullptr;
    cudaDriverEntryPointQueryResult qr;
    cudaGetDriverEntryPointByVersion("cuTensorMapEncodeTiled", (void**)&enc,
                                     12050, cudaEnableDefault, &qr);

    CUtensorMap tmA0, tmB0, tmA1, tmB1;
    make_map_fp16(enc, &tmA0, xh,  (unsigned long long)MTOT);
    make_map_fp16(enc, &tmB0, wt1, (unsigned long long)NQKV);
    make_map_fp16(enc, &tmA1, cth, (unsigned long long)MTOT);
    make_map_fp16(enc, &tmB1, wt2, (unsigned long long)HID);

    const int n4 = MTOT*HID/4;
    tohalf_kernel<<<(n4+1023)/1024, 1024>>>(x, xh, n4);
    transpose_kernel<<<dim3(NQKV/32, HID/32), 256>>>(Wqkv, wt1, HID, NQKV);
    transpose_kernel<<<dim3(HID/32,  HID/32), 256>>>(Wproj, wt2, HID, HID);

    hgemm<__half><<<dim3(NQKV/128, MTOT/128), 128, DSM_BYTES>>>(
        tmA0, tmB0, bqkv, qkvh, HID, NQKV);
    attn_kernel<<<MTOT, 128>>>();
    hgemm<float><<<dim3(HID/128, MTOT/128), 128, DSM_BYTES>>>(
        tmA1, tmB1, bproj, out, HID, HID);
}